// round 14
// baseline (speedup 1.0000x reference)
#include <cuda_runtime.h>
#include <math.h>

#define NN 2048
#define AA 100
#define BB 64
#define NTILE 32           // NN / BB (FW band grid)
#define OUT_SUM (NN*AA)
#define OUT_G   (NN*AA+1)
#define ASTR 132
#define P3_SMEM ((BB*ASTR + BB*128) * (int)sizeof(float))   // 66560 B
#define PB_SMEM (4 * 64 * 68 * (int)sizeof(float))          // 69632 B

// Scratch (static __device__ arrays — no allocation)
__device__ float d_dist[NN*NN];       // 16 MB distance matrix
__device__ int   d_anchors[AA];
__device__ float d_weighted[NN*AA];
__device__ float d_xx[NN];
__device__ float d_rowsum[NN];

__device__ __forceinline__ float finf() { return __int_as_float(0x7f800000); }

// ---------------------------------------------------------------------------
// Build w: adj = motif * nw[i] (row-scaled), w = min(f(adj), f(adj^T)), diag 0
// ---------------------------------------------------------------------------
__global__ void __launch_bounds__(256) k_build_w(const float* __restrict__ m,
                                                 const float* __restrict__ nw) {
    __shared__ float sT[32][33];
    int bi = blockIdx.y, bj = blockIdx.x;
    int tx = threadIdx.x & 31;
    int ty = threadIdx.x >> 5;
    #pragma unroll
    for (int rr = ty; rr < 32; rr += 8)
        sT[rr][tx] = m[(bj*32 + rr)*NN + bi*32 + tx];
    __syncthreads();
    #pragma unroll
    for (int rr = ty; rr < 32; rr += 8) {
        int i = bi*32 + rr;
        int j = bj*32 + tx;
        float a = m[i*NN + j] * nw[i];
        float b = sT[tx][rr] * nw[j];
        float wa = a > 0.f ? a : finf();
        float wb = b > 0.f ? b : finf();
        float w = fminf(wa, wb);
        if (i == j) w = 0.f;
        d_dist[i*NN + j] = w;
    }
}

// ---------------------------------------------------------------------------
// Fused phase1+2 (band k), R4-proven: all 64 blocks redundantly close pivot
// (k,k) in smem; bid<32 updates row panel (k,o), bid>=32 col panel (o,k).
// ---------------------------------------------------------------------------
__global__ void __launch_bounds__(256) fw_p12(int k) {
    __shared__ float Ps[BB][BB + 4];
    __shared__ float B1[BB][BB + 4];
    int tid = threadIdx.x;
    const int kB = k * BB;
    const int pbase = kB * NN + kB;

    #pragma unroll
    for (int e = tid; e < BB * BB; e += 256)
        Ps[e >> 6][e & 63] = d_dist[pbase + (e >> 6) * NN + (e & 63)];
    __syncthreads();

    int r  = tid >> 2;
    int c0 = (tid & 3) << 4;
    float cur[16];
    #pragma unroll
    for (int x = 0; x < 16; x++) cur[x] = Ps[r][c0 + x];

    for (int kk = 0; kk < BB; kk++) {
        float a = Ps[r][kk];
        float bv[16];
        #pragma unroll
        for (int q = 0; q < 4; q++) {
            float4 v = *(const float4*)&Ps[kk][c0 + q * 4];
            bv[q*4+0] = v.x; bv[q*4+1] = v.y; bv[q*4+2] = v.z; bv[q*4+3] = v.w;
        }
        #pragma unroll
        for (int x = 0; x < 16; x++)
            cur[x] = fminf(cur[x], a + bv[x]);
        #pragma unroll
        for (int q = 0; q < 4; q++)
            *(float4*)&Ps[r][c0 + q * 4] =
                make_float4(cur[q*4+0], cur[q*4+1], cur[q*4+2], cur[q*4+3]);
        __syncthreads();
    }

    int bid = blockIdx.x;
    int o = bid & 31;
    int tx = tid & 15, ty = tid >> 4;
    int rr0 = ty << 2, cc0 = tx << 2;
    float acc[4][4];
    #pragma unroll
    for (int a = 0; a < 4; a++)
        #pragma unroll
        for (int b = 0; b < 4; b++) acc[a][b] = finf();

    if (bid < 32) {
        #pragma unroll
        for (int x = 0; x < 16; x++) B1[c0 + x][r] = cur[x];   // P*^T
        #pragma unroll
        for (int e = tid; e < BB * BB; e += 256)
            Ps[e >> 6][e & 63] = d_dist[(kB + (e >> 6)) * NN + o * BB + (e & 63)];
        __syncthreads();
        #pragma unroll 4
        for (int p = 0; p < BB; p++) {
            float4 a4 = *(const float4*)&B1[p][rr0];
            float4 b4 = *(const float4*)&Ps[p][cc0];
            float av[4] = {a4.x, a4.y, a4.z, a4.w};
            float bv[4] = {b4.x, b4.y, b4.z, b4.w};
            #pragma unroll
            for (int a = 0; a < 4; a++)
                #pragma unroll
                for (int b = 0; b < 4; b++)
                    acc[a][b] = fminf(acc[a][b], av[a] + bv[b]);
        }
        #pragma unroll
        for (int a = 0; a < 4; a++)
            *(float4*)&d_dist[(kB + rr0 + a) * NN + o * BB + cc0] =
                make_float4(acc[a][0], acc[a][1], acc[a][2], acc[a][3]);
    } else {
        #pragma unroll
        for (int e = tid; e < BB * BB; e += 256) {
            int ii = e >> 6, p = e & 63;
            B1[p][ii] = d_dist[(o * BB + ii) * NN + kB + p];
        }
        __syncthreads();
        #pragma unroll 4
        for (int p = 0; p < BB; p++) {
            float4 a4 = *(const float4*)&B1[p][rr0];
            float4 b4 = *(const float4*)&Ps[p][cc0];
            float av[4] = {a4.x, a4.y, a4.z, a4.w};
            float bv[4] = {b4.x, b4.y, b4.z, b4.w};
            #pragma unroll
            for (int a = 0; a < 4; a++)
                #pragma unroll
                for (int b = 0; b < 4; b++)
                    acc[a][b] = fminf(acc[a][b], av[a] + bv[b]);
        }
        #pragma unroll
        for (int a = 0; a < 4; a++)
            *(float4*)&d_dist[(o * BB + rr0 + a) * NN + kB + cc0] =
                make_float4(acc[a][0], acc[a][1], acc[a][2], acc[a][3]);
    }
}

// ---------------------------------------------------------------------------
// Fused "crit + p12" for odd band k2 = 2k+1 (k1 = k2-1):
// each block (in smem): P(k2,k2) <- min(P, U (x) V) with U=C(k2,k1), V=C(k1,k2)
// (round-k1 pre-update), closes P -> P*, then for its panel tile applies the
// round-k1 chunk followed by the pivot closure. Pivot-tile write races are
// value-identical (= P*).
// ---------------------------------------------------------------------------
__global__ void __launch_bounds__(256) fw_p12b(int k2) {
    extern __shared__ float smb[];
    float* SP  = smb;               // [64][68] pivot (row-branch later: C)
    float* SUT = smb + 64*68;       // [64][68] U^T : SUT[p][i] = U[i][p]
    float* SB  = smb + 2*64*68;     // [64][68] V (row-branch later: C(k1,o))
    float* B1  = smb + 3*64*68;     // [64][68] P*^T (row) / C^T (col)
    int tid = threadIdx.x;
    const int k1 = k2 - 1;
    const int k1B = k1 * BB, k2B = k2 * BB;

    // Step 1: load P, U^T, V
    #pragma unroll
    for (int e = tid; e < BB * BB; e += 256) {
        int i = e >> 6, j = e & 63;
        SP [i*68 + j] = d_dist[(k2B + i) * NN + k2B + j];
        SUT[j*68 + i] = d_dist[(k2B + i) * NN + k1B + j];   // U[i][j] -> [j][i]
        SB [i*68 + j] = d_dist[(k1B + i) * NN + k2B + j];   // V
    }
    __syncthreads();

    int tx = tid & 15, ty = tid >> 4;
    int rr0 = ty << 2, cc0 = tx << 2;

    // Step 2: pivot pre-update P = min(P, U (x) V)
    {
        float acc[4][4];
        #pragma unroll
        for (int a = 0; a < 4; a++)
            #pragma unroll
            for (int b = 0; b < 4; b++)
                acc[a][b] = SP[(rr0 + a)*68 + cc0 + b];
        #pragma unroll 4
        for (int p = 0; p < BB; p++) {
            float4 a4 = *(const float4*)&SUT[p*68 + rr0];
            float4 b4 = *(const float4*)&SB [p*68 + cc0];
            float av[4] = {a4.x, a4.y, a4.z, a4.w};
            float bv[4] = {b4.x, b4.y, b4.z, b4.w};
            #pragma unroll
            for (int a = 0; a < 4; a++)
                #pragma unroll
                for (int b = 0; b < 4; b++)
                    acc[a][b] = fminf(acc[a][b], av[a] + bv[b]);
        }
        #pragma unroll
        for (int a = 0; a < 4; a++)
            #pragma unroll
            for (int b = 0; b < 4; b++)
                SP[(rr0 + a)*68 + cc0 + b] = acc[a][b];
        __syncthreads();
    }

    // Step 3: closure of SP (Gauss-Seidel)
    int r  = tid >> 2;
    int c0 = (tid & 3) << 4;
    float cur[16];
    #pragma unroll
    for (int x = 0; x < 16; x++) cur[x] = SP[r*68 + c0 + x];
    for (int kk = 0; kk < BB; kk++) {
        float a = SP[r*68 + kk];
        float bv[16];
        #pragma unroll
        for (int q = 0; q < 4; q++) {
            float4 v = *(const float4*)&SP[kk*68 + c0 + q*4];
            bv[q*4+0] = v.x; bv[q*4+1] = v.y; bv[q*4+2] = v.z; bv[q*4+3] = v.w;
        }
        #pragma unroll
        for (int x = 0; x < 16; x++)
            cur[x] = fminf(cur[x], a + bv[x]);
        #pragma unroll
        for (int q = 0; q < 4; q++)
            *(float4*)&SP[r*68 + c0 + q*4] =
                make_float4(cur[q*4+0], cur[q*4+1], cur[q*4+2], cur[q*4+3]);
        __syncthreads();
    }
    // SP = P*, cur = this thread's row segment of P*

    int bid = blockIdx.x;
    int o = bid & 31;
    const int oB = o * BB;
    float acc[4][4];

    if (bid < 32) {
        // Row tile C(k2, o)
        #pragma unroll
        for (int x = 0; x < 16; x++) B1[(c0 + x)*68 + r] = cur[x];   // P*^T
        #pragma unroll
        for (int e = tid; e < BB * BB; e += 256) {
            int p = e >> 6, j = e & 63;
            SB[p*68 + j] = d_dist[(k1B + p) * NN + oB + j];          // C(k1,o)
        }
        __syncthreads();
        #pragma unroll
        for (int a = 0; a < 4; a++) {
            float4 v = *(const float4*)&d_dist[(k2B + rr0 + a) * NN + oB + cc0];
            acc[a][0] = v.x; acc[a][1] = v.y; acc[a][2] = v.z; acc[a][3] = v.w;
        }
        // chunk k1: acc = min(acc, U (x) C(k1,o))
        #pragma unroll 4
        for (int p = 0; p < BB; p++) {
            float4 a4 = *(const float4*)&SUT[p*68 + rr0];
            float4 b4 = *(const float4*)&SB [p*68 + cc0];
            float av[4] = {a4.x, a4.y, a4.z, a4.w};
            float bv[4] = {b4.x, b4.y, b4.z, b4.w};
            #pragma unroll
            for (int a = 0; a < 4; a++)
                #pragma unroll
                for (int b = 0; b < 4; b++)
                    acc[a][b] = fminf(acc[a][b], av[a] + bv[b]);
        }
        // SP <- updated C (P* no longer needed as a matrix; P*^T lives in B1)
        #pragma unroll
        for (int a = 0; a < 4; a++)
            #pragma unroll
            for (int b = 0; b < 4; b++)
                SP[(rr0 + a)*68 + cc0 + b] = acc[a][b];
        __syncthreads();
        // pivot chunk: acc = min(acc, P* (x) C)
        #pragma unroll 4
        for (int p = 0; p < BB; p++) {
            float4 a4 = *(const float4*)&B1[p*68 + rr0];
            float4 b4 = *(const float4*)&SP[p*68 + cc0];
            float av[4] = {a4.x, a4.y, a4.z, a4.w};
            float bv[4] = {b4.x, b4.y, b4.z, b4.w};
            #pragma unroll
            for (int a = 0; a < 4; a++)
                #pragma unroll
                for (int b = 0; b < 4; b++)
                    acc[a][b] = fminf(acc[a][b], av[a] + bv[b]);
        }
        #pragma unroll
        for (int a = 0; a < 4; a++)
            *(float4*)&d_dist[(k2B + rr0 + a) * NN + oB + cc0] =
                make_float4(acc[a][0], acc[a][1], acc[a][2], acc[a][3]);
    } else {
        // Col tile C(o, k2); SP stays P*, SB stays V
        #pragma unroll
        for (int e = tid; e < BB * BB; e += 256) {
            int i = e >> 6, p = e & 63;
            B1[p*68 + i] = d_dist[(oB + i) * NN + k1B + p];          // C(o,k1)^T
        }
        __syncthreads();
        #pragma unroll
        for (int a = 0; a < 4; a++) {
            float4 v = *(const float4*)&d_dist[(oB + rr0 + a) * NN + k2B + cc0];
            acc[a][0] = v.x; acc[a][1] = v.y; acc[a][2] = v.z; acc[a][3] = v.w;
        }
        // chunk k1: acc = min(acc, C(o,k1) (x) V)
        #pragma unroll 4
        for (int p = 0; p < BB; p++) {
            float4 a4 = *(const float4*)&B1[p*68 + rr0];
            float4 b4 = *(const float4*)&SB[p*68 + cc0];
            float av[4] = {a4.x, a4.y, a4.z, a4.w};
            float bv[4] = {b4.x, b4.y, b4.z, b4.w};
            #pragma unroll
            for (int a = 0; a < 4; a++)
                #pragma unroll
                for (int b = 0; b < 4; b++)
                    acc[a][b] = fminf(acc[a][b], av[a] + bv[b]);
        }
        __syncthreads();
        // B1 <- C^T (updated)
        #pragma unroll
        for (int a = 0; a < 4; a++)
            #pragma unroll
            for (int b = 0; b < 4; b++)
                B1[(cc0 + b)*68 + rr0 + a] = acc[a][b];
        __syncthreads();
        // pivot chunk: acc = min(acc, C (x) P*): C[r][p] = B1[p][r], P*[p][c] = SP
        #pragma unroll 4
        for (int p = 0; p < BB; p++) {
            float4 a4 = *(const float4*)&B1[p*68 + rr0];
            float4 b4 = *(const float4*)&SP[p*68 + cc0];
            float av[4] = {a4.x, a4.y, a4.z, a4.w};
            float bv[4] = {b4.x, b4.y, b4.z, b4.w};
            #pragma unroll
            for (int a = 0; a < 4; a++)
                #pragma unroll
                for (int b = 0; b < 4; b++)
                    acc[a][b] = fminf(acc[a][b], av[a] + bv[b]);
        }
        #pragma unroll
        for (int a = 0; a < 4; a++)
            *(float4*)&d_dist[(oB + rr0 + a) * NN + k2B + cc0] =
                make_float4(acc[a][0], acc[a][1], acc[a][2], acc[a][3]);
    }
}

// ---------------------------------------------------------------------------
// Bulk phase3, two K-chunks per pass: C tile loaded/stored ONCE for bands
// kA and kA+1. 128x128 tiles, 8x8 microtile (R4-proven inner loop).
// ---------------------------------------------------------------------------
__global__ void __launch_bounds__(256, 2) fw_rest2(int kA) {
    extern __shared__ float sm[];
    float* AsT = sm;                    // [64][ASTR]
    float* Bs  = sm + BB * ASTR;        // [64][128]
    int tid = threadIdx.x;
    int bx = blockIdx.x, by = blockIdx.y;

    int tx = tid & 15, ty = tid >> 4;
    int r0 = ty << 3, c0 = tx << 3;
    const int cbase = (by * 128 + r0) * NN + bx * 128 + c0;
    float acc[8][8];
    #pragma unroll
    for (int a = 0; a < 8; a++) {
        float4 v0 = *(const float4*)&d_dist[cbase + a * NN];
        float4 v1 = *(const float4*)&d_dist[cbase + a * NN + 4];
        acc[a][0] = v0.x; acc[a][1] = v0.y; acc[a][2] = v0.z; acc[a][3] = v0.w;
        acc[a][4] = v1.x; acc[a][5] = v1.y; acc[a][6] = v1.z; acc[a][7] = v1.w;
    }

    for (int c = 0; c < 2; c++) {
        const int kB = (kA + c) * BB;
        __syncthreads();   // previous chunk's smem reads complete
        #pragma unroll
        for (int e = tid; e < 128 * 64; e += 256) {
            int rr = e >> 6, p = e & 63;
            AsT[p * ASTR + rr] = d_dist[(by * 128 + rr) * NN + kB + p];
        }
        #pragma unroll
        for (int e = tid; e < 64 * 128; e += 256) {
            int p = e >> 7, j = e & 127;
            Bs[p * 128 + j] = d_dist[(kB + p) * NN + bx * 128 + j];
        }
        __syncthreads();

        #pragma unroll 4
        for (int p = 0; p < BB; p++) {
            float4 a0 = *(const float4*)&AsT[p * ASTR + r0];
            float4 a1 = *(const float4*)&AsT[p * ASTR + r0 + 4];
            float4 b0 = *(const float4*)&Bs[p * 128 + c0];
            float4 b1 = *(const float4*)&Bs[p * 128 + c0 + 4];
            float av[8] = {a0.x, a0.y, a0.z, a0.w, a1.x, a1.y, a1.z, a1.w};
            float bv[8] = {b0.x, b0.y, b0.z, b0.w, b1.x, b1.y, b1.z, b1.w};
            #pragma unroll
            for (int a = 0; a < 8; a++)
                #pragma unroll
                for (int b = 0; b < 8; b++)
                    acc[a][b] = fminf(acc[a][b], av[a] + bv[b]);
        }
    }

    #pragma unroll
    for (int a = 0; a < 8; a++) {
        *(float4*)&d_dist[cbase + a * NN] =
            make_float4(acc[a][0], acc[a][1], acc[a][2], acc[a][3]);
        *(float4*)&d_dist[cbase + a * NN + 4] =
            make_float4(acc[a][4], acc[a][5], acc[a][6], acc[a][7]);
    }
}

// ---------------------------------------------------------------------------
// Anchors: exact stable argsort(-nw)[:100] via rank counting
// ---------------------------------------------------------------------------
__global__ void k_anchors(const float* __restrict__ nw) {
    __shared__ float s[NN];
    int tid = threadIdx.x;
    for (int e = tid; e < NN; e += 256) s[e] = nw[e];
    __syncthreads();
    int i = blockIdx.x * 256 + tid;
    float v = s[i];
    int rank = 0;
    for (int j = 0; j < NN; j++) {
        float u = s[j];
        rank += (u > v) || (u == v && j < i);
    }
    if (rank < AA) d_anchors[rank] = i;
}

// ---------------------------------------------------------------------------
__global__ void k_gather(const float* __restrict__ wm, float* __restrict__ out) {
    __shared__ int anc[AA];
    __shared__ float r1[128], r2[128];
    int i = blockIdx.x, tid = threadIdx.x;
    if (tid < AA) anc[tid] = d_anchors[tid];
    __syncthreads();
    float cv = 0.f, wsq = 0.f;
    if (tid < AA) {
        float v = d_dist[i * NN + anc[tid]];
        if (v > 3.0e38f) v = 100.f;
        out[i * AA + tid] = v;
        float w = wm[i * AA + tid] * v;
        d_weighted[i * AA + tid] = w;
        cv = v; wsq = w * w;
    }
    r1[tid] = cv; r2[tid] = wsq;
    __syncthreads();
    for (int st = 64; st > 0; st >>= 1) {
        if (tid < st) { r1[tid] += r1[tid + st]; r2[tid] += r2[tid + st]; }
        __syncthreads();
    }
    if (tid == 0) { d_rowsum[i] = r1[0]; d_xx[i] = r2[0]; }
}

__global__ void k_finalize(float* __restrict__ out) {
    __shared__ float red[256];
    int tid = threadIdx.x;
    float s = 0.f;
    for (int e = tid; e < NN; e += 256) s += d_rowsum[e];
    red[tid] = s;
    __syncthreads();
    for (int st = 128; st > 0; st >>= 1) {
        if (tid < st) red[tid] += red[tid + st];
        __syncthreads();
    }
    if (tid == 0) out[OUT_SUM] = (red[0] - 100.f * NN) / ((float)NN * AA);
}

// ---------------------------------------------------------------------------
__global__ void __launch_bounds__(256) k_graph(const float* __restrict__ sigma_p,
                                               float* __restrict__ out) {
    __shared__ float WiT[32][BB + 4];
    __shared__ float WjT[32][BB + 4];
    int bx = blockIdx.x, by = blockIdx.y;
    int tid = threadIdx.x, tx = tid & 15, ty = tid >> 4;
    int r0 = ty << 2, c0 = tx << 2;
    float acc[4][4] = {};
    for (int k0 = 0; k0 < 128; k0 += 32) {
        for (int e = tid; e < BB * 32; e += 256) {
            int rr = e >> 5, kc = e & 31;
            int kg = k0 + kc;
            float wi = 0.f, wj = 0.f;
            if (kg < AA) {
                wi = d_weighted[(by * BB + rr) * AA + kg];
                wj = d_weighted[(bx * BB + rr) * AA + kg];
            }
            WiT[kc][rr] = wi; WjT[kc][rr] = wj;
        }
        __syncthreads();
        #pragma unroll
        for (int kc = 0; kc < 32; kc++) {
            float4 a4 = *(const float4*)&WiT[kc][r0];
            float4 b4 = *(const float4*)&WjT[kc][c0];
            float av[4] = {a4.x, a4.y, a4.z, a4.w};
            float bv[4] = {b4.x, b4.y, b4.z, b4.w};
            #pragma unroll
            for (int a = 0; a < 4; a++)
                #pragma unroll
                for (int b = 0; b < 4; b++)
                    acc[a][b] += av[a] * bv[b];
        }
        __syncthreads();
    }
    float sg = *sigma_p;
    float inv2 = 0.5f / (sg * sg);
    float xi[4], xj[4];
    #pragma unroll
    for (int a = 0; a < 4; a++) xi[a] = d_xx[by * BB + r0 + a];
    #pragma unroll
    for (int b = 0; b < 4; b++) xj[b] = d_xx[bx * BB + c0 + b];
    #pragma unroll
    for (int a = 0; a < 4; a++) {
        int i = by * BB + r0 + a;
        #pragma unroll
        for (int b = 0; b < 4; b++) {
            int j = bx * BB + c0 + b;
            float sq = xi[a] + xj[b] - 2.f * acc[a][b];
            sq = fmaxf(sq, 0.f);
            out[OUT_G + i * NN + j] = expf(-(sq * sq) * inv2);
        }
    }
}

// ---------------------------------------------------------------------------
extern "C" void kernel_launch(void* const* d_in, const int* in_sizes, int n_in,
                              void* d_out, int out_size) {
    const float* m  = (const float*)d_in[0];
    const float* nw = (const float*)d_in[1];
    const float* wm = (const float*)d_in[2];
    const float* sg = (const float*)d_in[3];
    float* out = (float*)d_out;

    static int inited = 0;
    if (!inited) {
        cudaFuncSetAttribute(fw_rest2,
                             cudaFuncAttributeMaxDynamicSharedMemorySize, P3_SMEM);
        cudaFuncSetAttribute(fw_p12b,
                             cudaFuncAttributeMaxDynamicSharedMemorySize, PB_SMEM);
        inited = 1;
    }

    k_build_w<<<dim3(NN/32, NN/32), 256>>>(m, nw);
    k_anchors<<<NN / 256, 256>>>(nw);

    for (int s = 0; s < NTILE / 2; s++) {
        fw_p12<<<64, 256>>>(2 * s);
        fw_p12b<<<64, 256, PB_SMEM>>>(2 * s + 1);
        fw_rest2<<<dim3(16, 16), 256, P3_SMEM>>>(2 * s);
    }

    k_gather<<<NN, 128>>>(wm, out);
    k_finalize<<<1, 256>>>(out);
    k_graph<<<dim3(NTILE, NTILE), 256>>>(sg, out);
}

// round 15
// speedup vs baseline: 1.0182x; 1.0182x over previous
#include <cuda_runtime.h>
#include <math.h>

#define NN 2048
#define AA 100
#define BB 64
#define NTILE 32           // NN / BB (FW band grid)
#define OUT_SUM (NN*AA)
#define OUT_G   (NN*AA+1)
#define ASTR 132
#define P3_SMEM ((BB*ASTR + BB*128) * (int)sizeof(float))   // 66560 B

// Scratch (static __device__ arrays — no allocation)
__device__ float d_dist[NN*NN];       // 16 MB distance matrix
__device__ int   d_anchors[AA];
__device__ float d_weighted[NN*AA];
__device__ float d_xx[NN];
__device__ float d_rowsum[NN];

__device__ __forceinline__ float finf() { return __int_as_float(0x7f800000); }

// ---------------------------------------------------------------------------
// Build w: adj = motif * nw[i] (row-scaled), w = min(f(adj), f(adj^T)), diag 0
// ---------------------------------------------------------------------------
__global__ void __launch_bounds__(256) k_build_w(const float* __restrict__ m,
                                                 const float* __restrict__ nw) {
    __shared__ float sT[32][33];
    int bi = blockIdx.y, bj = blockIdx.x;
    int tx = threadIdx.x & 31;
    int ty = threadIdx.x >> 5;
    #pragma unroll
    for (int rr = ty; rr < 32; rr += 8)
        sT[rr][tx] = m[(bj*32 + rr)*NN + bi*32 + tx];
    __syncthreads();
    #pragma unroll
    for (int rr = ty; rr < 32; rr += 8) {
        int i = bi*32 + rr;
        int j = bj*32 + tx;
        float a = m[i*NN + j] * nw[i];
        float b = sT[tx][rr] * nw[j];
        float wa = a > 0.f ? a : finf();
        float wb = b > 0.f ? b : finf();
        float w = fminf(wa, wb);
        if (i == j) w = 0.f;
        d_dist[i*NN + j] = w;
    }
}

// ---------------------------------------------------------------------------
// Fused phase1+2 (band k), R4-proven: all 64 blocks redundantly close pivot
// (k,k) in smem; bid<32 updates row panel (k,o), bid>=32 col panel (o,k).
// ---------------------------------------------------------------------------
__global__ void __launch_bounds__(256) fw_p12(int k) {
    __shared__ float Ps[BB][BB + 4];
    __shared__ float B1[BB][BB + 4];
    int tid = threadIdx.x;
    const int kB = k * BB;
    const int pbase = kB * NN + kB;

    #pragma unroll
    for (int e = tid; e < BB * BB; e += 256)
        Ps[e >> 6][e & 63] = d_dist[pbase + (e >> 6) * NN + (e & 63)];
    __syncthreads();

    int r  = tid >> 2;
    int c0 = (tid & 3) << 4;
    float cur[16];
    #pragma unroll
    for (int x = 0; x < 16; x++) cur[x] = Ps[r][c0 + x];

    for (int kk = 0; kk < BB; kk++) {
        float a = Ps[r][kk];
        float bv[16];
        #pragma unroll
        for (int q = 0; q < 4; q++) {
            float4 v = *(const float4*)&Ps[kk][c0 + q * 4];
            bv[q*4+0] = v.x; bv[q*4+1] = v.y; bv[q*4+2] = v.z; bv[q*4+3] = v.w;
        }
        #pragma unroll
        for (int x = 0; x < 16; x++)
            cur[x] = fminf(cur[x], a + bv[x]);
        #pragma unroll
        for (int q = 0; q < 4; q++)
            *(float4*)&Ps[r][c0 + q * 4] =
                make_float4(cur[q*4+0], cur[q*4+1], cur[q*4+2], cur[q*4+3]);
        __syncthreads();
    }

    int bid = blockIdx.x;
    int o = bid & 31;
    int tx = tid & 15, ty = tid >> 4;
    int rr0 = ty << 2, cc0 = tx << 2;
    float acc[4][4];
    #pragma unroll
    for (int a = 0; a < 4; a++)
        #pragma unroll
        for (int b = 0; b < 4; b++) acc[a][b] = finf();

    if (bid < 32) {
        #pragma unroll
        for (int x = 0; x < 16; x++) B1[c0 + x][r] = cur[x];   // P*^T
        #pragma unroll
        for (int e = tid; e < BB * BB; e += 256)
            Ps[e >> 6][e & 63] = d_dist[(kB + (e >> 6)) * NN + o * BB + (e & 63)];
        __syncthreads();
        #pragma unroll 4
        for (int p = 0; p < BB; p++) {
            float4 a4 = *(const float4*)&B1[p][rr0];
            float4 b4 = *(const float4*)&Ps[p][cc0];
            float av[4] = {a4.x, a4.y, a4.z, a4.w};
            float bv[4] = {b4.x, b4.y, b4.z, b4.w};
            #pragma unroll
            for (int a = 0; a < 4; a++)
                #pragma unroll
                for (int b = 0; b < 4; b++)
                    acc[a][b] = fminf(acc[a][b], av[a] + bv[b]);
        }
        #pragma unroll
        for (int a = 0; a < 4; a++)
            *(float4*)&d_dist[(kB + rr0 + a) * NN + o * BB + cc0] =
                make_float4(acc[a][0], acc[a][1], acc[a][2], acc[a][3]);
    } else {
        #pragma unroll
        for (int e = tid; e < BB * BB; e += 256) {
            int ii = e >> 6, p = e & 63;
            B1[p][ii] = d_dist[(o * BB + ii) * NN + kB + p];
        }
        __syncthreads();
        #pragma unroll 4
        for (int p = 0; p < BB; p++) {
            float4 a4 = *(const float4*)&B1[p][rr0];
            float4 b4 = *(const float4*)&Ps[p][cc0];
            float av[4] = {a4.x, a4.y, a4.z, a4.w};
            float bv[4] = {b4.x, b4.y, b4.z, b4.w};
            #pragma unroll
            for (int a = 0; a < 4; a++)
                #pragma unroll
                for (int b = 0; b < 4; b++)
                    acc[a][b] = fminf(acc[a][b], av[a] + bv[b]);
        }
        #pragma unroll
        for (int a = 0; a < 4; a++)
            *(float4*)&d_dist[(o * BB + rr0 + a) * NN + kB + cc0] =
                make_float4(acc[a][0], acc[a][1], acc[a][2], acc[a][3]);
    }
}

// ---------------------------------------------------------------------------
// Critical band update for round k: bring band k+1 to round-k completeness.
// Row tiles (k+1, o) all o; col tiles (o, k+1) o != k+1. 64x64 tiles, one
// min-plus GEMM each: C = min(C, A(.,k) (+,min) B(k,.)).  (R6-proven.)
// ---------------------------------------------------------------------------
__global__ void __launch_bounds__(256) fw_crit(int k) {
    int bid = blockIdx.x;
    int k1 = k + 1;
    int o = bid & 31;
    bool rowTile = bid < 32;
    if (!rowTile && o == k1) return;       // avoid duplicate (k+1,k+1)
    int ti = rowTile ? k1 : o;
    int tj = rowTile ? o  : k1;
    __shared__ float AsT[BB][BB + 4];
    __shared__ float Bs [BB][BB + 4];
    int tid = threadIdx.x;
    const int kB = k * BB;
    const int abase = (ti * BB) * NN + kB;
    const int bbase = kB * NN + tj * BB;
    #pragma unroll
    for (int e = tid; e < BB * BB; e += 256) {
        int rr = e >> 6, cc = e & 63;
        AsT[cc][rr] = d_dist[abase + rr * NN + cc];
        Bs [rr][cc] = d_dist[bbase + rr * NN + cc];
    }
    int tx = tid & 15, ty = tid >> 4;
    int r0 = ty << 2, c0 = tx << 2;
    const int cbase = (ti * BB + r0) * NN + tj * BB + c0;
    float acc[4][4];
    #pragma unroll
    for (int a = 0; a < 4; a++) {
        float4 v = *(const float4*)&d_dist[cbase + a * NN];
        acc[a][0] = v.x; acc[a][1] = v.y; acc[a][2] = v.z; acc[a][3] = v.w;
    }
    __syncthreads();
    #pragma unroll 4
    for (int p = 0; p < BB; p++) {
        float4 a4 = *(const float4*)&AsT[p][r0];
        float4 b4 = *(const float4*)&Bs[p][c0];
        float av[4] = {a4.x, a4.y, a4.z, a4.w};
        float bv[4] = {b4.x, b4.y, b4.z, b4.w};
        #pragma unroll
        for (int a = 0; a < 4; a++)
            #pragma unroll
            for (int b = 0; b < 4; b++)
                acc[a][b] = fminf(acc[a][b], av[a] + bv[b]);
    }
    #pragma unroll
    for (int a = 0; a < 4; a++)
        *(float4*)&d_dist[cbase + a * NN] =
            make_float4(acc[a][0], acc[a][1], acc[a][2], acc[a][3]);
}

// ---------------------------------------------------------------------------
// Bulk phase3, two K-chunks per pass (R14-measured ~37us): C tile loaded and
// stored ONCE for bands kA and kA+1. 128x128 tiles, 8x8 microtile.
// ---------------------------------------------------------------------------
__global__ void __launch_bounds__(256, 2) fw_rest2(int kA) {
    extern __shared__ float sm[];
    float* AsT = sm;                    // [64][ASTR]
    float* Bs  = sm + BB * ASTR;        // [64][128]
    int tid = threadIdx.x;
    int bx = blockIdx.x, by = blockIdx.y;

    int tx = tid & 15, ty = tid >> 4;
    int r0 = ty << 3, c0 = tx << 3;
    const int cbase = (by * 128 + r0) * NN + bx * 128 + c0;
    float acc[8][8];
    #pragma unroll
    for (int a = 0; a < 8; a++) {
        float4 v0 = *(const float4*)&d_dist[cbase + a * NN];
        float4 v1 = *(const float4*)&d_dist[cbase + a * NN + 4];
        acc[a][0] = v0.x; acc[a][1] = v0.y; acc[a][2] = v0.z; acc[a][3] = v0.w;
        acc[a][4] = v1.x; acc[a][5] = v1.y; acc[a][6] = v1.z; acc[a][7] = v1.w;
    }

    for (int c = 0; c < 2; c++) {
        const int kB = (kA + c) * BB;
        __syncthreads();   // previous chunk's smem reads complete
        #pragma unroll
        for (int e = tid; e < 128 * 64; e += 256) {
            int rr = e >> 6, p = e & 63;
            AsT[p * ASTR + rr] = d_dist[(by * 128 + rr) * NN + kB + p];
        }
        #pragma unroll
        for (int e = tid; e < 64 * 128; e += 256) {
            int p = e >> 7, j = e & 127;
            Bs[p * 128 + j] = d_dist[(kB + p) * NN + bx * 128 + j];
        }
        __syncthreads();

        #pragma unroll 4
        for (int p = 0; p < BB; p++) {
            float4 a0 = *(const float4*)&AsT[p * ASTR + r0];
            float4 a1 = *(const float4*)&AsT[p * ASTR + r0 + 4];
            float4 b0 = *(const float4*)&Bs[p * 128 + c0];
            float4 b1 = *(const float4*)&Bs[p * 128 + c0 + 4];
            float av[8] = {a0.x, a0.y, a0.z, a0.w, a1.x, a1.y, a1.z, a1.w};
            float bv[8] = {b0.x, b0.y, b0.z, b0.w, b1.x, b1.y, b1.z, b1.w};
            #pragma unroll
            for (int a = 0; a < 8; a++)
                #pragma unroll
                for (int b = 0; b < 8; b++)
                    acc[a][b] = fminf(acc[a][b], av[a] + bv[b]);
        }
    }

    #pragma unroll
    for (int a = 0; a < 8; a++) {
        *(float4*)&d_dist[cbase + a * NN] =
            make_float4(acc[a][0], acc[a][1], acc[a][2], acc[a][3]);
        *(float4*)&d_dist[cbase + a * NN + 4] =
            make_float4(acc[a][4], acc[a][5], acc[a][6], acc[a][7]);
    }
}

// ---------------------------------------------------------------------------
// Anchors: exact stable argsort(-nw)[:100] via rank counting
// ---------------------------------------------------------------------------
__global__ void k_anchors(const float* __restrict__ nw) {
    __shared__ float s[NN];
    int tid = threadIdx.x;
    for (int e = tid; e < NN; e += 256) s[e] = nw[e];
    __syncthreads();
    int i = blockIdx.x * 256 + tid;
    float v = s[i];
    int rank = 0;
    for (int j = 0; j < NN; j++) {
        float u = s[j];
        rank += (u > v) || (u == v && j < i);
    }
    if (rank < AA) d_anchors[rank] = i;
}

// ---------------------------------------------------------------------------
__global__ void k_gather(const float* __restrict__ wm, float* __restrict__ out) {
    __shared__ int anc[AA];
    __shared__ float r1[128], r2[128];
    int i = blockIdx.x, tid = threadIdx.x;
    if (tid < AA) anc[tid] = d_anchors[tid];
    __syncthreads();
    float cv = 0.f, wsq = 0.f;
    if (tid < AA) {
        float v = d_dist[i * NN + anc[tid]];
        if (v > 3.0e38f) v = 100.f;
        out[i * AA + tid] = v;
        float w = wm[i * AA + tid] * v;
        d_weighted[i * AA + tid] = w;
        cv = v; wsq = w * w;
    }
    r1[tid] = cv; r2[tid] = wsq;
    __syncthreads();
    for (int st = 64; st > 0; st >>= 1) {
        if (tid < st) { r1[tid] += r1[tid + st]; r2[tid] += r2[tid + st]; }
        __syncthreads();
    }
    if (tid == 0) { d_rowsum[i] = r1[0]; d_xx[i] = r2[0]; }
}

__global__ void k_finalize(float* __restrict__ out) {
    __shared__ float red[256];
    int tid = threadIdx.x;
    float s = 0.f;
    for (int e = tid; e < NN; e += 256) s += d_rowsum[e];
    red[tid] = s;
    __syncthreads();
    for (int st = 128; st > 0; st >>= 1) {
        if (tid < st) red[tid] += red[tid + st];
        __syncthreads();
    }
    if (tid == 0) out[OUT_SUM] = (red[0] - 100.f * NN) / ((float)NN * AA);
}

// ---------------------------------------------------------------------------
__global__ void __launch_bounds__(256) k_graph(const float* __restrict__ sigma_p,
                                               float* __restrict__ out) {
    __shared__ float WiT[32][BB + 4];
    __shared__ float WjT[32][BB + 4];
    int bx = blockIdx.x, by = blockIdx.y;
    int tid = threadIdx.x, tx = tid & 15, ty = tid >> 4;
    int r0 = ty << 2, c0 = tx << 2;
    float acc[4][4] = {};
    for (int k0 = 0; k0 < 128; k0 += 32) {
        for (int e = tid; e < BB * 32; e += 256) {
            int rr = e >> 5, kc = e & 31;
            int kg = k0 + kc;
            float wi = 0.f, wj = 0.f;
            if (kg < AA) {
                wi = d_weighted[(by * BB + rr) * AA + kg];
                wj = d_weighted[(bx * BB + rr) * AA + kg];
            }
            WiT[kc][rr] = wi; WjT[kc][rr] = wj;
        }
        __syncthreads();
        #pragma unroll
        for (int kc = 0; kc < 32; kc++) {
            float4 a4 = *(const float4*)&WiT[kc][r0];
            float4 b4 = *(const float4*)&WjT[kc][c0];
            float av[4] = {a4.x, a4.y, a4.z, a4.w};
            float bv[4] = {b4.x, b4.y, b4.z, b4.w};
            #pragma unroll
            for (int a = 0; a < 4; a++)
                #pragma unroll
                for (int b = 0; b < 4; b++)
                    acc[a][b] += av[a] * bv[b];
        }
        __syncthreads();
    }
    float sg = *sigma_p;
    float inv2 = 0.5f / (sg * sg);
    float xi[4], xj[4];
    #pragma unroll
    for (int a = 0; a < 4; a++) xi[a] = d_xx[by * BB + r0 + a];
    #pragma unroll
    for (int b = 0; b < 4; b++) xj[b] = d_xx[bx * BB + c0 + b];
    #pragma unroll
    for (int a = 0; a < 4; a++) {
        int i = by * BB + r0 + a;
        #pragma unroll
        for (int b = 0; b < 4; b++) {
            int j = bx * BB + c0 + b;
            float sq = xi[a] + xj[b] - 2.f * acc[a][b];
            sq = fmaxf(sq, 0.f);
            out[OUT_G + i * NN + j] = expf(-(sq * sq) * inv2);
        }
    }
}

// ---------------------------------------------------------------------------
extern "C" void kernel_launch(void* const* d_in, const int* in_sizes, int n_in,
                              void* d_out, int out_size) {
    const float* m  = (const float*)d_in[0];
    const float* nw = (const float*)d_in[1];
    const float* wm = (const float*)d_in[2];
    const float* sg = (const float*)d_in[3];
    float* out = (float*)d_out;

    static int inited = 0;
    if (!inited) {
        cudaFuncSetAttribute(fw_rest2,
                             cudaFuncAttributeMaxDynamicSharedMemorySize, P3_SMEM);
        inited = 1;
    }

    k_build_w<<<dim3(NN/32, NN/32), 256>>>(m, nw);
    k_anchors<<<NN / 256, 256>>>(nw);

    for (int s = 0; s < NTILE / 2; s++) {
        fw_p12<<<64, 256>>>(2 * s);          // close band 2s
        fw_crit<<<64, 256>>>(2 * s);         // band 2s+1 -> round-2s complete
        fw_p12<<<64, 256>>>(2 * s + 1);      // close band 2s+1
        fw_rest2<<<dim3(16, 16), 256, P3_SMEM>>>(2 * s);   // both chunks
    }

    k_gather<<<NN, 128>>>(wm, out);
    k_finalize<<<1, 256>>>(out);
    k_graph<<<dim3(NTILE, NTILE), 256>>>(sg, out);
}